// round 13
// baseline (speedup 1.0000x reference)
#include <cuda_runtime.h>
#include <math.h>
#include <stdint.h>

// Problem constants (V=8192, F=256, B=32, L=64)
#define VV     8192
#define FF     256
#define BBATCH 32
#define LLEN   64
#define RR     2016
#define RPAD   2048
#define BM     128
#define BN     128
#define KC     32
#define NW     8           // 256 bits = 8 x u32 words
#define NWF    2           // words in partial filter (64 bits)
#define CUTOFF 20.0f       // drop logit deficits > 20 (rel err <= 1.2e-4 worst case)
#define NT     64          // fallback n-tiles (BN=128)
#define PCN    64          // pc path: n-cols per tile
#define PCNT   128         // pc path: n-tiles
#define NGRP   4           // pc path: n-tiles per CTA
#define NTMAX  128         // pm/ps stride
#define MT     16          // m-tiles
#define VMASK  (VV - 1)
#define PREPB  (VV / 8)    // 1024 packing blocks; block PREPB = cfg + seq

struct Cfg { float w0, W, w0x2, thresh, wfc, delta; int flag, ihhi; };

__device__ Cfg      g_cfg;
__device__ int      g_use_pc = 1;   // reset by k_fin each call
__device__ int      g_ticket = 0;   // reset by k_fin each call
__device__ uint32_t g_Bbits[VV * NW];
__device__ int      g_useq[RPAD];
__device__ int      g_tgt[RPAD];
__device__ float    g_sfeat[VV];
__device__ float    g_pm[RPAD * NTMAX];
__device__ float    g_ps[RPAD * NTMAX];
__device__ float    g_rownll[RPAD];

__device__ __forceinline__ float neg_inf() { return __int_as_float(0xff800000u); }

__device__ __forceinline__ uint32_t smem_u32(const void* p) {
    uint32_t a;
    asm("{ .reg .u64 t; cvta.to.shared.u64 t, %1; cvt.u32.u64 %0, t; }" : "=r"(a) : "l"(p));
    return a;
}
#define MBAR_INIT(mb, cnt) asm volatile("mbarrier.init.shared.b64 [%0], %1;" :: "r"(mb), "r"(cnt) : "memory")
#define MBAR_EXPECT_TX(mb, bytes) asm volatile("mbarrier.arrive.expect_tx.shared.b64 _, [%0], %1;" :: "r"(mb), "r"(bytes) : "memory")
#define MBAR_WAIT(mb, ph) do {                                                  \
    uint32_t _m = (mb), _p = (ph), _d;                                          \
    asm volatile("{\n\t.reg .pred p;\n\t"                                       \
        "mbarrier.try_wait.parity.acquire.cta.shared::cta.b64 p, [%1], %2;\n\t" \
        "selp.b32 %0, 1, 0, p;\n\t}" : "=r"(_d) : "r"(_m), "r"(_p) : "memory"); \
    if (!_d) {                                                                  \
        asm volatile("{\n\t.reg .pred P1;\n\t"                                  \
            "WL_%=:\n\t"                                                        \
            "mbarrier.try_wait.parity.acquire.cta.shared::cta.b64 P1, [%0], %1, 0x989680;\n\t" \
            "@P1 bra.uni WD_%=;\n\t bra.uni WL_%=;\n\t WD_%=:\n\t}"             \
            :: "r"(_m), "r"(_p) : "memory");                                    \
    } } while (0)
#define BULK_G2S(smem_dst, gmem_src, bytes, mb)                                 \
    asm volatile("cp.async.bulk.shared::cta.global.mbarrier::complete_tx::bytes " \
        "[%0], [%1], %2, [%3];"                                                 \
        :: "r"(smem_dst), "l"(gmem_src), "r"(bytes), "r"(mb) : "memory")

__device__ __forceinline__ uint32_t nib_of(int4 x) {
    return (uint32_t)(x.x != 0) | ((uint32_t)(x.y != 0) << 1)
         | ((uint32_t)(x.z != 0) << 2) | ((uint32_t)(x.w != 0) << 3);
}
__device__ __forceinline__ int bin_ok(int4 x) {
    return ((x.x | x.y | x.z | x.w) & ~1) == 0 &&
           x.x >= 0 && x.y >= 0 && x.z >= 0 && x.w >= 0;
}

// ---------------------------------------------------------------------------
// PREP: grid = PREPB + 1 blocks, 256 threads. (unchanged from R12)
// ---------------------------------------------------------------------------
__global__ void k_prep(const int* __restrict__ feat, const float* __restrict__ w,
                       const int* __restrict__ seq32) {
    const int bid = blockIdx.x, tid = threadIdx.x;

    if (bid < PREPB) {
        __shared__ __align__(16) int sbuf[8 * FF];   // 8 KB
        __shared__ __align__(8) unsigned long long s_mbar;

        const uint32_t mb = smem_u32(&s_mbar);
        if (tid == 0) {
            MBAR_INIT(mb, 1);
            asm volatile("fence.proxy.async.shared::cta;" ::: "memory");
            MBAR_EXPECT_TX(mb, 8 * FF * 4);
            BULK_G2S(smem_u32(sbuf), &feat[(size_t)bid * 8 * FF], 8 * FF * 4, mb);
        }
        __syncthreads();
        MBAR_WAIT(mb, 0);

        const int grp = tid >> 6;
        const int t   = tid & 63;
        const int v0  = bid * 8 + grp;

        int4 x0 = *(const int4*)&sbuf[(grp    ) * FF + t * 4];
        int4 x1 = *(const int4*)&sbuf[(grp + 4) * FF + t * 4];
        float wx = w[1 + t * 4 + 0], wy = w[1 + t * 4 + 1];
        float wz = w[1 + t * 4 + 2], ww = w[1 + t * 4 + 3];

        uint32_t n0 = nib_of(x0) << ((t & 7) * 4);
        uint32_t n1 = nib_of(x1) << ((t & 7) * 4);
        #pragma unroll
        for (int o = 1; o < 8; o <<= 1) {
            n0 |= __shfl_xor_sync(0xffffffffu, n0, o);
            n1 |= __shfl_xor_sync(0xffffffffu, n1, o);
        }
        if ((t & 7) == 0) {
            g_Bbits[(v0    ) * NW + (t >> 3)] = n0;
            g_Bbits[(v0 + 4) * NW + (t >> 3)] = n1;
        }

        int ok = bin_ok(x0) && bin_ok(x1);
        if (!__syncthreads_and(ok)) {
            if (tid == 0) atomicAnd(&g_use_pc, 0);
        }

        float p0 = wx * (float)x0.x + wy * (float)x0.y + wz * (float)x0.z + ww * (float)x0.w;
        float p1 = wx * (float)x1.x + wy * (float)x1.y + wz * (float)x1.z + ww * (float)x1.w;
        #pragma unroll
        for (int o = 16; o; o >>= 1) {
            p0 += __shfl_down_sync(0xffffffffu, p0, o);
            p1 += __shfl_down_sync(0xffffffffu, p1, o);
        }
        __shared__ float sred[8][2];
        if ((t & 31) == 0) {
            sred[grp    ][t >> 5] = p0;
            sred[grp + 4][t >> 5] = p1;
        }
        __syncthreads();
        if (tid < 8) g_sfeat[bid * 8 + tid] = sred[tid][0] + sred[tid][1];
        return;
    }

    // ------- tail block: scalar config + sequence decode -------
    {
        float wf = w[1 + tid];
        float s = wf, mn = wf, mx = wf;
        #pragma unroll
        for (int o = 16; o; o >>= 1) {
            s  += __shfl_down_sync(0xffffffffu, s, o);
            mn  = fminf(mn, __shfl_down_sync(0xffffffffu, mn, o));
            mx  = fmaxf(mx, __shfl_down_sync(0xffffffffu, mx, o));
        }
        __shared__ float ssum[8], smin[8], smax[8];
        __shared__ int s_st;
        if ((tid & 31) == 0) { ssum[tid >> 5] = s; smin[tid >> 5] = mn; smax[tid >> 5] = mx; }
        if (tid < 32) {
            int odd = seq32[2 * tid + 1];
            uint32_t nz = __ballot_sync(0xffffffffu, odd != 0);
            if (tid == 0) s_st = (nz == 0) ? 2 : 1;
        }
        __syncthreads();
        if (tid == 0) {
            float S = 0.f, MN = 3.0e38f, MX = -3.0e38f;
            #pragma unroll
            for (int i = 0; i < 8; i++) {
                S += ssum[i]; MN = fminf(MN, smin[i]); MX = fmaxf(MX, smax[i]);
            }
            float w0 = w[0];
            Cfg c;
            c.w0 = w0; c.W = S; c.w0x2 = 2.0f * w0;
            c.flag = (w0 >= 0.f && MN >= 0.f) ? 1 : 0;
            c.thresh = w0 * S - 33.0f;
            c.wfc = MN;
            c.delta = w0 * MN;
            if (c.delta > 0.f) {
                float hf = CUTOFF / c.delta;
                c.ihhi = (hf >= 256.f) ? 256 : (int)hf;
            } else {
                c.ihhi = 256;
            }
            g_cfg = c;
            atomicAnd(&g_use_pc, (MN == MX && c.flag) ? 1 : 0);
        }
        const int st = s_st;
        #pragma unroll
        for (int it = 0; it < 8; it++) {
            int r = it * 256 + tid;
            if (r < RR) {
                int b = r / (LLEN - 1), t2 = r % (LLEN - 1);
                g_useq[r] = seq32[(b * LLEN + t2) * st] & VMASK;
                g_tgt[r]  = seq32[(b * LLEN + t2 + 1) * st] & VMASK;
            } else {
                g_useq[r] = 0; g_tgt[r] = 0;
            }
        }
    }
}

// ---------------------------------------------------------------------------
// MAIN: grid (32, 16), 256 threads. Union smem (32 KB). One resident wave.
// pc path:  CTA owns m-tile by and NGRP=4 n-tiles. sA + exp-table staged
//           ONCE; loop over n-tiles {stage sB, 2-word filter, rescue, ps}.
// fallback: fp32 SIMT GEMM; CTA loops over 2 n-tiles of BN=128.
// ---------------------------------------------------------------------------
__global__ __launch_bounds__(256, 4) void k_main(const int* __restrict__ feat,
                                                 const float* __restrict__ w) {
    __shared__ __align__(16) char U[32768];
    const int tid = threadIdx.x;
    const Cfg c = g_cfg;

    if (g_use_pc) {
        uint32_t (*sA)[NW] = (uint32_t(*)[NW])(U);            // 4096 B
        uint32_t (*sB)[NW] = (uint32_t(*)[NW])(U + 4096);     // 2048 B
        float* tbl         = (float*)(U + 6144);              // 1028 B
        float (*red)[8]    = (float(*)[8])(U + 7200);         // 4096 B

        const int tx = tid & 7, ty = tid >> 3;
        const int m0 = blockIdx.y * BM;
        const float delta = c.delta;
        const int   ihhi  = c.ihhi;

        tbl[tid] = __expf(-delta * (float)tid);
        if (tid == 0) tbl[256] = __expf(-delta * 256.f);

        // stage sA once (shared by all NGRP n-tiles)
        {
            int r = tid >> 1, h = (tid & 1) << 2;
            int sw = (r >> 2) & 7;
            int u = g_useq[m0 + r];
            uint4 a = *(const uint4*)&g_Bbits[(size_t)u * NW + h];
            sA[r][(h + 0) ^ sw] = a.x; sA[r][(h + 1) ^ sw] = a.y;
            sA[r][(h + 2) ^ sw] = a.z; sA[r][(h + 3) ^ sw] = a.w;
        }
        const int swa = ty & 7;

        #pragma unroll 1
        for (int g = 0; g < NGRP; g++) {
            const int ncol = blockIdx.x * NGRP + g;
            const int n0 = ncol * PCN;

            if (tid < 128) {
                int r = tid >> 1, h = (tid & 1) << 2;
                int sw = (r >> 3) & 7;
                uint4 b = *(const uint4*)&g_Bbits[(size_t)(n0 + r) * NW + h];
                sB[r][(h + 0) ^ sw] = b.x; sB[r][(h + 1) ^ sw] = b.y;
                sB[r][(h + 2) ^ sw] = b.z; sB[r][(h + 3) ^ sw] = b.w;
            }
            __syncthreads();

            int acc[4][8];
            #pragma unroll
            for (int i = 0; i < 4; i++)
                #pragma unroll
                for (int j = 0; j < 8; j++) acc[i][j] = 0;

            // partial hamming over words 0..NWF-1 (lower bound on total)
            #pragma unroll
            for (int wi = 0; wi < NWF; wi++) {
                uint32_t av[4], bv[8];
                #pragma unroll
                for (int i = 0; i < 4; i++) av[i] = sA[ty * 4 + i][wi ^ swa];
                #pragma unroll
                for (int j = 0; j < 8; j++) bv[j] = sB[tx * 8 + j][wi ^ tx];
                #pragma unroll
                for (int i = 0; i < 4; i++)
                    #pragma unroll
                    for (int j = 0; j < 8; j++)
                        acc[i][j] += __popc(av[i] ^ bv[j]);
            }

            int hmin = acc[0][0];
            #pragma unroll
            for (int i = 0; i < 4; i++)
                #pragma unroll
                for (int j = 0; j < 8; j++) hmin = min(hmin, acc[i][j]);

            float s[4] = {0.f, 0.f, 0.f, 0.f};
            if (hmin <= ihhi) {
                #pragma unroll
                for (int i = 0; i < 4; i++) {
                    #pragma unroll
                    for (int j = 0; j < 8; j++) {
                        if (acc[i][j] <= ihhi) {
                            int h = acc[i][j];
                            #pragma unroll
                            for (int wi = NWF; wi < 8; wi++)
                                h += __popc(sA[ty * 4 + i][wi ^ swa] ^ sB[tx * 8 + j][wi ^ tx]);
                            s[i] += tbl[h];
                        }
                    }
                }
            }
            #pragma unroll
            for (int i = 0; i < 4; i++) red[ty * 4 + i][tx] = s[i];
            __syncthreads();

            if (tid < BM) {
                float ss = 0.f;
                #pragma unroll
                for (int k = 0; k < 8; k++) ss += red[tid][k];
                g_ps[(size_t)(m0 + tid) * NTMAX + ncol] = ss;
            }
            __syncthreads();   // protect sB/red before next iteration
        }
        return;
    }

    // ---------------- fallback fp32 GEMM (2 n-tiles per CTA) ----------------
    float (*As)[BM] = (float(*)[BM])(U);            // 16 KB
    float (*Bs)[BN] = (float(*)[BN])(U + 16384);    // 16 KB

    const int tx = tid & 15, ty = tid >> 4;
    const int m0 = blockIdx.y * BM;
    const int ldrow = tid >> 3;
    const int ldc   = (tid & 7) << 2;

    #pragma unroll 1
    for (int g = 0; g < 2; g++) {
        const int ncol = blockIdx.x * 2 + g;
        const int n0 = ncol * BN;

        float acc[8][8];
        #pragma unroll
        for (int i = 0; i < 8; i++)
            #pragma unroll
            for (int j = 0; j < 8; j++) acc[i][j] = 0.f;

        for (int k0 = 0; k0 < FF; k0 += KC) {
            float w0c = w[1 + k0 + ldc + 0], w1c = w[1 + k0 + ldc + 1];
            float w2c = w[1 + k0 + ldc + 2], w3c = w[1 + k0 + ldc + 3];
            #pragma unroll
            for (int q = 0; q < 4; q++) {
                int row = ldrow + q * 32;
                int ua = g_useq[m0 + row];
                int4 a = *(const int4*)&feat[(size_t)ua * FF + k0 + ldc];
                As[ldc + 0][row] = w0c * (float)a.x; As[ldc + 1][row] = w1c * (float)a.y;
                As[ldc + 2][row] = w2c * (float)a.z; As[ldc + 3][row] = w3c * (float)a.w;
                int4 b = *(const int4*)&feat[(size_t)(n0 + row) * FF + k0 + ldc];
                Bs[ldc + 0][row] = (float)b.x; Bs[ldc + 1][row] = (float)b.y;
                Bs[ldc + 2][row] = (float)b.z; Bs[ldc + 3][row] = (float)b.w;
            }
            __syncthreads();
            #pragma unroll
            for (int k = 0; k < KC; k++) {
                float4 a0 = *(const float4*)&As[k][ty * 8];
                float4 a1 = *(const float4*)&As[k][ty * 8 + 4];
                float4 b0 = *(const float4*)&Bs[k][tx * 8];
                float4 b1 = *(const float4*)&Bs[k][tx * 8 + 4];
                float av[8] = {a0.x, a0.y, a0.z, a0.w, a1.x, a1.y, a1.z, a1.w};
                float bv[8] = {b0.x, b0.y, b0.z, b0.w, b1.x, b1.y, b1.z, b1.w};
                #pragma unroll
                for (int i = 0; i < 8; i++)
                    #pragma unroll
                    for (int j = 0; j < 8; j++)
                        acc[i][j] = fmaf(av[i], bv[j], acc[i][j]);
            }
            __syncthreads();
        }

        float (*red_m)[16] = (float(*)[16])(U);          // reuse As/Bs region
        float (*red_s)[16] = (float(*)[16])(U + 8192);

        float sv[8];
        #pragma unroll
        for (int j = 0; j < 8; j++) sv[j] = g_sfeat[n0 + tx * 8 + j];

        #pragma unroll
        for (int i = 0; i < 8; i++) {
            int m = ty * 8 + i;
            int uu = g_useq[m0 + m];
            float rb = c.w0 * (c.W - g_sfeat[uu]);
            float mi = neg_inf(), si = 0.f;
            #pragma unroll
            for (int j = 0; j < 8; j++) {
                float x = c.w0x2 * acc[i][j] - c.w0 * sv[j] + rb;
                if (!c.flag || x > c.thresh) {
                    if (x > mi) { si = si * __expf(mi - x) + 1.0f; mi = x; }
                    else        { si += __expf(x - mi); }
                }
            }
            red_m[m][tx] = mi;
            red_s[m][tx] = si;
        }
        __syncthreads();

        if (tid < BM) {
            float mm = neg_inf(), ss = 0.f;
            #pragma unroll
            for (int k = 0; k < 16; k++) {
                float mk = red_m[tid][k], sk = red_s[tid][k];
                if (sk > 0.f) {
                    if (mk > mm) { ss = ss * __expf(mm - mk) + sk; mm = mk; }
                    else         { ss += sk * __expf(mk - mm); }
                }
            }
            g_pm[(size_t)(m0 + tid) * NTMAX + ncol] = mm;
            g_ps[(size_t)(m0 + tid) * NTMAX + ncol] = ss;
        }
        __syncthreads();   // protect As/Bs (aliased by red_m/red_s) for next g
    }
}

// ---------------------------------------------------------------------------
// FIN: grid 63 x 1024 (one warp per row). Last block reduces row NLLs in
// fixed order, writes the scalar, resets globals for graph replay.
// ---------------------------------------------------------------------------
__global__ void k_fin(const int* __restrict__ feat, const float* __restrict__ w,
                      float* __restrict__ out) {
    __shared__ int s_last;
    int tid = threadIdx.x, lane = tid & 31, wid = tid >> 5;
    int r = blockIdx.x * 32 + wid;
    const int use_pc = g_use_pc;

    {
        float lse;
        int tg = g_tgt[r];
        float xt;
        if (use_pc) {
            float s = 0.f;
            #pragma unroll
            for (int q = 0; q < 4; q++) s += g_ps[(size_t)r * NTMAX + lane + 32 * q];
            #pragma unroll
            for (int o = 16; o; o >>= 1) s += __shfl_down_sync(0xffffffffu, s, o);
            lse = g_cfg.delta * 256.f + logf(s);
            int u = g_useq[r];
            int h = (lane < NW)
                  ? __popc(g_Bbits[u * NW + lane] ^ g_Bbits[tg * NW + lane]) : 0;
            #pragma unroll
            for (int o = 16; o; o >>= 1) h += __shfl_down_sync(0xffffffffu, h, o);
            xt = g_cfg.delta * (256.f - (float)h);
        } else {
            float mm = neg_inf(), ss = 0.f;
            #pragma unroll
            for (int q = 0; q < 2; q++) {
                int k = lane + 32 * q;
                float mk = g_pm[(size_t)r * NTMAX + k], sk = g_ps[(size_t)r * NTMAX + k];
                if (sk > 0.f) {
                    if (mk > mm) { ss = ss * __expf(mm - mk) + sk; mm = mk; }
                    else         { ss += sk * __expf(mk - mm); }
                }
            }
            #pragma unroll
            for (int o = 16; o; o >>= 1) {
                float mo = __shfl_down_sync(0xffffffffu, mm, o);
                float so = __shfl_down_sync(0xffffffffu, ss, o);
                if (so > 0.f) {
                    if (mo > mm) { ss = ss * __expf(mm - mo) + so; mm = mo; }
                    else         { ss += so * __expf(mo - mm); }
                }
            }
            lse = mm + logf(ss);
            int u = g_useq[r];
            float dot = 0.f;
            #pragma unroll
            for (int q = 0; q < 2; q++) {
                int f0 = q * 128 + lane * 4;
                int4 a = *(const int4*)&feat[(size_t)u  * FF + f0];
                int4 b = *(const int4*)&feat[(size_t)tg * FF + f0];
                dot += w[1 + f0 + 0] * (float)(a.x * b.x) + w[1 + f0 + 1] * (float)(a.y * b.y)
                     + w[1 + f0 + 2] * (float)(a.z * b.z) + w[1 + f0 + 3] * (float)(a.w * b.w);
            }
            #pragma unroll
            for (int o = 16; o; o >>= 1) dot += __shfl_down_sync(0xffffffffu, dot, o);
            float rb = g_cfg.w0 * (g_cfg.W - g_sfeat[u]);
            xt = g_cfg.w0x2 * dot - g_cfg.w0 * g_sfeat[tg] + rb;
        }
        if (lane == 0) g_rownll[r] = lse - xt;
    }

    __syncthreads();
    if (tid == 0) {
        __threadfence();
        int t = atomicAdd(&g_ticket, 1);
        s_last = (t == gridDim.x - 1);
    }
    __syncthreads();
    if (s_last) {
        __threadfence();
        __shared__ float red[1024];
        float v = 0.f;
        if (tid < RR)        v += g_rownll[tid];
        if (tid + 1024 < RR) v += g_rownll[tid + 1024];
        red[tid] = v;
        __syncthreads();
        #pragma unroll
        for (int s = 512; s > 0; s >>= 1) {
            if (tid < s) red[tid] += red[tid + s];
            __syncthreads();
        }
        if (tid == 0) {
            out[0] = red[0] + (float)BBATCH * logf((float)VV);
            g_ticket = 0;     // reset for next graph replay
            g_use_pc = 1;
        }
    }
}

// ---------------------------------------------------------------------------
extern "C" void kernel_launch(void* const* d_in, const int* in_sizes, int n_in,
                              void* d_out, int out_size) {
    const float* w    = 0;
    const int*   feat = 0;
    const int*   seq  = 0;
    for (int i = 0; i < n_in; i++) {
        if      (in_sizes[i] == FF + 1)        w    = (const float*)d_in[i];
        else if (in_sizes[i] == VV * FF)       feat = (const int*)d_in[i];
        else if (in_sizes[i] == BBATCH * LLEN) seq  = (const int*)d_in[i];
    }
    if (!w || !feat || !seq) {
        w    = (const float*)d_in[0];
        feat = (const int*)d_in[1];
        seq  = (const int*)d_in[2];
    }

    k_prep<<<PREPB + 1, 256>>>(feat, w, seq);
    k_main<<<dim3(PCNT / NGRP, MT), 256>>>(feat, w);
    k_fin<<<63, 1024>>>(feat, w, (float*)d_out);
}

// round 14
// speedup vs baseline: 1.0795x; 1.0795x over previous
#include <cuda_runtime.h>
#include <math.h>
#include <stdint.h>

// Problem constants (V=8192, F=256, B=32, L=64)
#define VV     8192
#define FF     256
#define BBATCH 32
#define LLEN   64
#define RR     2016
#define RPAD   2048
#define BM     128
#define BN     128
#define KC     32
#define NW     8           // 256 bits = 8 x u32 words
#define NWF    2           // words in partial filter (64 bits)
#define CUTOFF 20.0f       // drop logit deficits > 20 (rel err <= 1.2e-4 worst case)
#define NT     64          // fallback n-tiles (BN=128)
#define PCN    64          // pc path: n-cols per CTA
#define PCNT   128         // pc path: n-tiles
#define NTMAX  128         // pm/ps stride
#define MT     16          // m-tiles
#define VMASK  (VV - 1)
#define ROWSB  32          // vocab rows packed per prep block
#define PREPB  (VV / ROWSB) // 256 packing blocks; block PREPB = cfg + seq

struct Cfg { float w0, W, w0x2, thresh, wfc, delta; int flag, ihhi; };

__device__ Cfg      g_cfg;
__device__ int      g_use_pc = 1;   // reset by k_fin each call
__device__ int      g_ticket = 0;   // reset by k_fin each call
__device__ uint32_t g_Bbits[VV * NW];
__device__ int      g_useq[RPAD];
__device__ int      g_tgt[RPAD];
__device__ float    g_sfeat[VV];
__device__ float    g_pm[RPAD * NTMAX];
__device__ float    g_ps[RPAD * NTMAX];
__device__ float    g_rownll[RPAD];

__device__ __forceinline__ float neg_inf() { return __int_as_float(0xff800000u); }

__device__ __forceinline__ uint32_t smem_u32(const void* p) {
    uint32_t a;
    asm("{ .reg .u64 t; cvta.to.shared.u64 t, %1; cvt.u32.u64 %0, t; }" : "=r"(a) : "l"(p));
    return a;
}
#define MBAR_INIT(mb, cnt) asm volatile("mbarrier.init.shared.b64 [%0], %1;" :: "r"(mb), "r"(cnt) : "memory")
#define MBAR_EXPECT_TX(mb, bytes) asm volatile("mbarrier.arrive.expect_tx.shared.b64 _, [%0], %1;" :: "r"(mb), "r"(bytes) : "memory")
#define MBAR_WAIT(mb, ph) do {                                                  \
    uint32_t _m = (mb), _p = (ph), _d;                                          \
    asm volatile("{\n\t.reg .pred p;\n\t"                                       \
        "mbarrier.try_wait.parity.acquire.cta.shared::cta.b64 p, [%1], %2;\n\t" \
        "selp.b32 %0, 1, 0, p;\n\t}" : "=r"(_d) : "r"(_m), "r"(_p) : "memory"); \
    if (!_d) {                                                                  \
        asm volatile("{\n\t.reg .pred P1;\n\t"                                  \
            "WL_%=:\n\t"                                                        \
            "mbarrier.try_wait.parity.acquire.cta.shared::cta.b64 P1, [%0], %1, 0x989680;\n\t" \
            "@P1 bra.uni WD_%=;\n\t bra.uni WL_%=;\n\t WD_%=:\n\t}"             \
            :: "r"(_m), "r"(_p) : "memory");                                    \
    } } while (0)
#define BULK_G2S(smem_dst, gmem_src, bytes, mb)                                 \
    asm volatile("cp.async.bulk.shared::cta.global.mbarrier::complete_tx::bytes " \
        "[%0], [%1], %2, [%3];"                                                 \
        :: "r"(smem_dst), "l"(gmem_src), "r"(bytes), "r"(mb) : "memory")

__device__ __forceinline__ uint32_t nib_of(int4 x) {
    return (uint32_t)(x.x != 0) | ((uint32_t)(x.y != 0) << 1)
         | ((uint32_t)(x.z != 0) << 2) | ((uint32_t)(x.w != 0) << 3);
}
__device__ __forceinline__ int bin_ok(int4 x) {
    return ((x.x | x.y | x.z | x.w) & ~1) == 0 &&
           x.x >= 0 && x.y >= 0 && x.z >= 0 && x.w >= 0;
}

// ---------------------------------------------------------------------------
// PREP: grid = PREPB + 1 blocks, 256 threads.
// Blocks [0, PREPB): ONE 32 KB bulk copy (32 vocab rows) global->smem, then
//                    pack bits / s_feat / binarity in 4 chunks of 8 rows.
// Block PREPB:       scalar cfg + seq decode.
// ---------------------------------------------------------------------------
__global__ void k_prep(const int* __restrict__ feat, const float* __restrict__ w,
                       const int* __restrict__ seq32) {
    const int bid = blockIdx.x, tid = threadIdx.x;

    if (bid < PREPB) {
        __shared__ __align__(16) int sbuf[ROWSB * FF];   // 32 KB
        __shared__ __align__(8) unsigned long long s_mbar;
        __shared__ float sred[8][2];

        const uint32_t mb = smem_u32(&s_mbar);
        if (tid == 0) {
            MBAR_INIT(mb, 1);
            asm volatile("fence.proxy.async.shared::cta;" ::: "memory");
            MBAR_EXPECT_TX(mb, ROWSB * FF * 4);
            BULK_G2S(smem_u32(sbuf), &feat[(size_t)bid * ROWSB * FF],
                     ROWSB * FF * 4, mb);
        }
        __syncthreads();
        MBAR_WAIT(mb, 0);

        const int grp = tid >> 6;            // 0..3
        const int t   = tid & 63;            // thread within row (4 feats each)
        // hoisted weight loads (w+1 only 4B-aligned -> scalar)
        const float wx = w[1 + t * 4 + 0], wy = w[1 + t * 4 + 1];
        const float wz = w[1 + t * 4 + 2], ww = w[1 + t * 4 + 3];

        int ok_all = 1;
        #pragma unroll
        for (int ch = 0; ch < ROWSB / 8; ch++) {
            const int r0 = ch * 8 + grp;         // smem row (first of pair)
            const int v0 = bid * ROWSB + r0;     // global vocab row

            int4 x0 = *(const int4*)&sbuf[(r0    ) * FF + t * 4];
            int4 x1 = *(const int4*)&sbuf[(r0 + 4) * FF + t * 4];

            uint32_t n0 = nib_of(x0) << ((t & 7) * 4);
            uint32_t n1 = nib_of(x1) << ((t & 7) * 4);
            #pragma unroll
            for (int o = 1; o < 8; o <<= 1) {
                n0 |= __shfl_xor_sync(0xffffffffu, n0, o);
                n1 |= __shfl_xor_sync(0xffffffffu, n1, o);
            }
            if ((t & 7) == 0) {
                g_Bbits[(v0    ) * NW + (t >> 3)] = n0;
                g_Bbits[(v0 + 4) * NW + (t >> 3)] = n1;
            }

            ok_all &= bin_ok(x0) && bin_ok(x1);

            float p0 = wx * (float)x0.x + wy * (float)x0.y
                     + wz * (float)x0.z + ww * (float)x0.w;
            float p1 = wx * (float)x1.x + wy * (float)x1.y
                     + wz * (float)x1.z + ww * (float)x1.w;
            #pragma unroll
            for (int o = 16; o; o >>= 1) {
                p0 += __shfl_down_sync(0xffffffffu, p0, o);
                p1 += __shfl_down_sync(0xffffffffu, p1, o);
            }
            if ((t & 31) == 0) {
                sred[grp    ][t >> 5] = p0;
                sred[grp + 4][t >> 5] = p1;
            }
            __syncthreads();
            if (tid < 8) g_sfeat[bid * ROWSB + ch * 8 + tid] = sred[tid][0] + sred[tid][1];
            __syncthreads();
        }

        if (!__syncthreads_and(ok_all)) {
            if (tid == 0) atomicAnd(&g_use_pc, 0);
        }
        return;
    }

    // ------- tail block: scalar config + sequence decode -------
    {
        float wf = w[1 + tid];
        float s = wf, mn = wf, mx = wf;
        #pragma unroll
        for (int o = 16; o; o >>= 1) {
            s  += __shfl_down_sync(0xffffffffu, s, o);
            mn  = fminf(mn, __shfl_down_sync(0xffffffffu, mn, o));
            mx  = fmaxf(mx, __shfl_down_sync(0xffffffffu, mx, o));
        }
        __shared__ float ssum[8], smin[8], smax[8];
        __shared__ int s_st;
        if ((tid & 31) == 0) { ssum[tid >> 5] = s; smin[tid >> 5] = mn; smax[tid >> 5] = mx; }
        if (tid < 32) {
            int odd = seq32[2 * tid + 1];
            uint32_t nz = __ballot_sync(0xffffffffu, odd != 0);
            if (tid == 0) s_st = (nz == 0) ? 2 : 1;
        }
        __syncthreads();
        if (tid == 0) {
            float S = 0.f, MN = 3.0e38f, MX = -3.0e38f;
            #pragma unroll
            for (int i = 0; i < 8; i++) {
                S += ssum[i]; MN = fminf(MN, smin[i]); MX = fmaxf(MX, smax[i]);
            }
            float w0 = w[0];
            Cfg c;
            c.w0 = w0; c.W = S; c.w0x2 = 2.0f * w0;
            c.flag = (w0 >= 0.f && MN >= 0.f) ? 1 : 0;
            c.thresh = w0 * S - 33.0f;
            c.wfc = MN;
            c.delta = w0 * MN;
            if (c.delta > 0.f) {
                float hf = CUTOFF / c.delta;
                c.ihhi = (hf >= 256.f) ? 256 : (int)hf;
            } else {
                c.ihhi = 256;
            }
            g_cfg = c;
            atomicAnd(&g_use_pc, (MN == MX && c.flag) ? 1 : 0);
        }
        const int st = s_st;
        #pragma unroll
        for (int it = 0; it < 8; it++) {
            int r = it * 256 + tid;
            if (r < RR) {
                int b = r / (LLEN - 1), t2 = r % (LLEN - 1);
                g_useq[r] = seq32[(b * LLEN + t2) * st] & VMASK;
                g_tgt[r]  = seq32[(b * LLEN + t2 + 1) * st] & VMASK;
            } else {
                g_useq[r] = 0; g_tgt[r] = 0;
            }
        }
    }
}

// ---------------------------------------------------------------------------
// MAIN: grid (PCNT, MT) = 2048 CTAs, 256 threads. Union smem (32 KB).
// (R12 configuration — independent CTAs maximize latency overlap.)
// pc path:  2-word partial-hamming filter (64 bits; false-pass ~2e-3)
//           + rescue completing words 2..7 + exp-table; writes ps only.
// fallback: fp32 SIMT GEMM (blocks with bx < NT) + online LSE; writes pm+ps.
// ---------------------------------------------------------------------------
__global__ __launch_bounds__(256, 4) void k_main(const int* __restrict__ feat,
                                                 const float* __restrict__ w) {
    __shared__ __align__(16) char U[32768];
    const int tid = threadIdx.x;
    const Cfg c = g_cfg;

    if (g_use_pc) {
        uint32_t (*sA)[NW] = (uint32_t(*)[NW])(U);            // 4096 B
        uint32_t (*sB)[NW] = (uint32_t(*)[NW])(U + 4096);     // 2048 B
        float* tbl         = (float*)(U + 6144);              // 1028 B
        float (*red)[8]    = (float(*)[8])(U + 7200);         // 4096 B

        const int tx = tid & 7, ty = tid >> 3;
        const int n0 = blockIdx.x * PCN, m0 = blockIdx.y * BM;
        const float delta = c.delta;
        const int   ihhi  = c.ihhi;

        tbl[tid] = __expf(-delta * (float)tid);
        if (tid == 0) tbl[256] = __expf(-delta * 256.f);

        {
            int r = tid >> 1, h = (tid & 1) << 2;
            int sw = (r >> 2) & 7;
            int u = g_useq[m0 + r];
            uint4 a = *(const uint4*)&g_Bbits[(size_t)u * NW + h];
            sA[r][(h + 0) ^ sw] = a.x; sA[r][(h + 1) ^ sw] = a.y;
            sA[r][(h + 2) ^ sw] = a.z; sA[r][(h + 3) ^ sw] = a.w;
        }
        if (tid < 128) {
            int r = tid >> 1, h = (tid & 1) << 2;
            int sw = (r >> 3) & 7;
            uint4 b = *(const uint4*)&g_Bbits[(size_t)(n0 + r) * NW + h];
            sB[r][(h + 0) ^ sw] = b.x; sB[r][(h + 1) ^ sw] = b.y;
            sB[r][(h + 2) ^ sw] = b.z; sB[r][(h + 3) ^ sw] = b.w;
        }
        __syncthreads();

        int acc[4][8];
        #pragma unroll
        for (int i = 0; i < 4; i++)
            #pragma unroll
            for (int j = 0; j < 8; j++) acc[i][j] = 0;

        const int swa = ty & 7;
        // partial hamming over words 0..NWF-1 (lower bound on total)
        #pragma unroll
        for (int wi = 0; wi < NWF; wi++) {
            uint32_t av[4], bv[8];
            #pragma unroll
            for (int i = 0; i < 4; i++) av[i] = sA[ty * 4 + i][wi ^ swa];
            #pragma unroll
            for (int j = 0; j < 8; j++) bv[j] = sB[tx * 8 + j][wi ^ tx];
            #pragma unroll
            for (int i = 0; i < 4; i++)
                #pragma unroll
                for (int j = 0; j < 8; j++)
                    acc[i][j] += __popc(av[i] ^ bv[j]);
        }

        int hmin = acc[0][0];
        #pragma unroll
        for (int i = 0; i < 4; i++)
            #pragma unroll
            for (int j = 0; j < 8; j++) hmin = min(hmin, acc[i][j]);

        float s[4] = {0.f, 0.f, 0.f, 0.f};
        if (hmin <= ihhi) {
            #pragma unroll
            for (int i = 0; i < 4; i++) {
                #pragma unroll
                for (int j = 0; j < 8; j++) {
                    if (acc[i][j] <= ihhi) {
                        int h = acc[i][j];
                        #pragma unroll
                        for (int wi = NWF; wi < 8; wi++)
                            h += __popc(sA[ty * 4 + i][wi ^ swa] ^ sB[tx * 8 + j][wi ^ tx]);
                        s[i] += tbl[h];
                    }
                }
            }
        }
        #pragma unroll
        for (int i = 0; i < 4; i++) red[ty * 4 + i][tx] = s[i];
        __syncthreads();

        if (tid < BM) {
            float ss = 0.f;
            #pragma unroll
            for (int k = 0; k < 8; k++) ss += red[tid][k];
            g_ps[(size_t)(m0 + tid) * NTMAX + blockIdx.x] = ss;
        }
        return;
    }

    // ---------------- fallback fp32 GEMM ----------------
    if (blockIdx.x >= NT) return;
    float (*As)[BM] = (float(*)[BM])(U);            // 16 KB
    float (*Bs)[BN] = (float(*)[BN])(U + 16384);    // 16 KB

    const int tx = tid & 15, ty = tid >> 4;
    const int m0 = blockIdx.y * BM, n0 = blockIdx.x * BN;
    const int ldrow = tid >> 3;
    const int ldc   = (tid & 7) << 2;

    float acc[8][8];
    #pragma unroll
    for (int i = 0; i < 8; i++)
        #pragma unroll
        for (int j = 0; j < 8; j++) acc[i][j] = 0.f;

    for (int k0 = 0; k0 < FF; k0 += KC) {
        float w0c = w[1 + k0 + ldc + 0], w1c = w[1 + k0 + ldc + 1];
        float w2c = w[1 + k0 + ldc + 2], w3c = w[1 + k0 + ldc + 3];
        #pragma unroll
        for (int q = 0; q < 4; q++) {
            int row = ldrow + q * 32;
            int ua = g_useq[m0 + row];
            int4 a = *(const int4*)&feat[(size_t)ua * FF + k0 + ldc];
            As[ldc + 0][row] = w0c * (float)a.x; As[ldc + 1][row] = w1c * (float)a.y;
            As[ldc + 2][row] = w2c * (float)a.z; As[ldc + 3][row] = w3c * (float)a.w;
            int4 b = *(const int4*)&feat[(size_t)(n0 + row) * FF + k0 + ldc];
            Bs[ldc + 0][row] = (float)b.x; Bs[ldc + 1][row] = (float)b.y;
            Bs[ldc + 2][row] = (float)b.z; Bs[ldc + 3][row] = (float)b.w;
        }
        __syncthreads();
        #pragma unroll
        for (int k = 0; k < KC; k++) {
            float4 a0 = *(const float4*)&As[k][ty * 8];
            float4 a1 = *(const float4*)&As[k][ty * 8 + 4];
            float4 b0 = *(const float4*)&Bs[k][tx * 8];
            float4 b1 = *(const float4*)&Bs[k][tx * 8 + 4];
            float av[8] = {a0.x, a0.y, a0.z, a0.w, a1.x, a1.y, a1.z, a1.w};
            float bv[8] = {b0.x, b0.y, b0.z, b0.w, b1.x, b1.y, b1.z, b1.w};
            #pragma unroll
            for (int i = 0; i < 8; i++)
                #pragma unroll
                for (int j = 0; j < 8; j++)
                    acc[i][j] = fmaf(av[i], bv[j], acc[i][j]);
        }
        __syncthreads();
    }

    float (*red_m)[16] = (float(*)[16])(U);          // reuse As/Bs region
    float (*red_s)[16] = (float(*)[16])(U + 8192);

    float sv[8];
    #pragma unroll
    for (int j = 0; j < 8; j++) sv[j] = g_sfeat[n0 + tx * 8 + j];

    #pragma unroll
    for (int i = 0; i < 8; i++) {
        int m = ty * 8 + i;
        int uu = g_useq[m0 + m];
        float rb = c.w0 * (c.W - g_sfeat[uu]);
        float mi = neg_inf(), si = 0.f;
        #pragma unroll
        for (int j = 0; j < 8; j++) {
            float x = c.w0x2 * acc[i][j] - c.w0 * sv[j] + rb;
            if (!c.flag || x > c.thresh) {
                if (x > mi) { si = si * __expf(mi - x) + 1.0f; mi = x; }
                else        { si += __expf(x - mi); }
            }
        }
        red_m[m][tx] = mi;
        red_s[m][tx] = si;
    }
    __syncthreads();

    if (tid < BM) {
        float mm = neg_inf(), ss = 0.f;
        #pragma unroll
        for (int k = 0; k < 16; k++) {
            float mk = red_m[tid][k], sk = red_s[tid][k];
            if (sk > 0.f) {
                if (mk > mm) { ss = ss * __expf(mm - mk) + sk; mm = mk; }
                else         { ss += sk * __expf(mk - mm); }
            }
        }
        g_pm[(size_t)(m0 + tid) * NTMAX + blockIdx.x] = mm;
        g_ps[(size_t)(m0 + tid) * NTMAX + blockIdx.x] = ss;
    }
}

// ---------------------------------------------------------------------------
// FIN: grid 63 x 1024 (one warp per row). Last block reduces row NLLs in
// fixed order, writes the scalar, resets globals for graph replay.
// ---------------------------------------------------------------------------
__global__ void k_fin(const int* __restrict__ feat, const float* __restrict__ w,
                      float* __restrict__ out) {
    __shared__ int s_last;
    int tid = threadIdx.x, lane = tid & 31, wid = tid >> 5;
    int r = blockIdx.x * 32 + wid;
    const int use_pc = g_use_pc;

    {
        float lse;
        int tg = g_tgt[r];
        float xt;
        if (use_pc) {
            float s = 0.f;
            #pragma unroll
            for (int q = 0; q < 4; q++) s += g_ps[(size_t)r * NTMAX + lane + 32 * q];
            #pragma unroll
            for (int o = 16; o; o >>= 1) s += __shfl_down_sync(0xffffffffu, s, o);
            lse = g_cfg.delta * 256.f + logf(s);
            int u = g_useq[r];
            int h = (lane < NW)
                  ? __popc(g_Bbits[u * NW + lane] ^ g_Bbits[tg * NW + lane]) : 0;
            #pragma unroll
            for (int o = 16; o; o >>= 1) h += __shfl_down_sync(0xffffffffu, h, o);
            xt = g_cfg.delta * (256.f - (float)h);
        } else {
            float mm = neg_inf(), ss = 0.f;
            #pragma unroll
            for (int q = 0; q < 2; q++) {
                int k = lane + 32 * q;
                float mk = g_pm[(size_t)r * NTMAX + k], sk = g_ps[(size_t)r * NTMAX + k];
                if (sk > 0.f) {
                    if (mk > mm) { ss = ss * __expf(mm - mk) + sk; mm = mk; }
                    else         { ss += sk * __expf(mk - mm); }
                }
            }
            #pragma unroll
            for (int o = 16; o; o >>= 1) {
                float mo = __shfl_down_sync(0xffffffffu, mm, o);
                float so = __shfl_down_sync(0xffffffffu, ss, o);
                if (so > 0.f) {
                    if (mo > mm) { ss = ss * __expf(mm - mo) + so; mm = mo; }
                    else         { ss += so * __expf(mo - mm); }
                }
            }
            lse = mm + logf(ss);
            int u = g_useq[r];
            float dot = 0.f;
            #pragma unroll
            for (int q = 0; q < 2; q++) {
                int f0 = q * 128 + lane * 4;
                int4 a = *(const int4*)&feat[(size_t)u  * FF + f0];
                int4 b = *(const int4*)&feat[(size_t)tg * FF + f0];
                dot += w[1 + f0 + 0] * (float)(a.x * b.x) + w[1 + f0 + 1] * (float)(a.y * b.y)
                     + w[1 + f0 + 2] * (float)(a.z * b.z) + w[1 + f0 + 3] * (float)(a.w * b.w);
            }
            #pragma unroll
            for (int o = 16; o; o >>= 1) dot += __shfl_down_sync(0xffffffffu, dot, o);
            float rb = g_cfg.w0 * (g_cfg.W - g_sfeat[u]);
            xt = g_cfg.w0x2 * dot - g_cfg.w0 * g_sfeat[tg] + rb;
        }
        if (lane == 0) g_rownll[r] = lse - xt;
    }

    __syncthreads();
    if (tid == 0) {
        __threadfence();
        int t = atomicAdd(&g_ticket, 1);
        s_last = (t == gridDim.x - 1);
    }
    __syncthreads();
    if (s_last) {
        __threadfence();
        __shared__ float red[1024];
        float v = 0.f;
        if (tid < RR)        v += g_rownll[tid];
        if (tid + 1024 < RR) v += g_rownll[tid + 1024];
        red[tid] = v;
        __syncthreads();
        #pragma unroll
        for (int s = 512; s > 0; s >>= 1) {
            if (tid < s) red[tid] += red[tid + s];
            __syncthreads();
        }
        if (tid == 0) {
            out[0] = red[0] + (float)BBATCH * logf((float)VV);
            g_ticket = 0;     // reset for next graph replay
            g_use_pc = 1;
        }
    }
}

// ---------------------------------------------------------------------------
extern "C" void kernel_launch(void* const* d_in, const int* in_sizes, int n_in,
                              void* d_out, int out_size) {
    const float* w    = 0;
    const int*   feat = 0;
    const int*   seq  = 0;
    for (int i = 0; i < n_in; i++) {
        if      (in_sizes[i] == FF + 1)        w    = (const float*)d_in[i];
        else if (in_sizes[i] == VV * FF)       feat = (const int*)d_in[i];
        else if (in_sizes[i] == BBATCH * LLEN) seq  = (const int*)d_in[i];
    }
    if (!w || !feat || !seq) {
        w    = (const float*)d_in[0];
        feat = (const int*)d_in[1];
        seq  = (const int*)d_in[2];
    }

    k_prep<<<PREPB + 1, 256>>>(feat, w, seq);
    k_main<<<dim3(PCNT, MT), 256>>>(feat, w);
    k_fin<<<63, 1024>>>(feat, w, (float*)d_out);
}